// round 1
// baseline (speedup 1.0000x reference)
#include <cuda_runtime.h>
#include <math.h>

// Problem dims (fixed by the reference)
#define NB 4
#define NL 4096
#define ND 1024
#define NFF 2048
#define NM (NB * NL)          // 16384 rows
#define NT 128                // conv chunk length
#define NC (NL / NT)          // 32 chunks
#define LN_EPS 1e-5f

// ---------------------------------------------------------------------------
// Static scratch (no cudaMalloc allowed)
// ---------------------------------------------------------------------------
__device__ float g_xn[NM * ND];     // LN(x)
__device__ float g_conv[NM * ND];   // spiral conv (real part)
__device__ float g_y[NM * ND];      // silu(x@fc_w + fc_b)
__device__ float g_x2[NM * ND];     // c*y + x
__device__ float g_x3[NM * ND];     // LN(x2)
__device__ float g_t1[NM * NFF];    // silu(x3@w1 + b1)

__device__ float2 g_E[NB * NC * ND];      // chunk-local end states
__device__ float2 g_carry[NB * NC * ND];  // incoming state per chunk
__device__ float2 g_phz[ND];              // phz
__device__ float2 g_phzT[ND];             // phz^T
__device__ float2 g_Q[NC * ND];           // phz^(j*T + 1)

// ---------------------------------------------------------------------------
// Block reduce for LayerNorm (256 threads = 8 warps)
// ---------------------------------------------------------------------------
__device__ __forceinline__ float2 block_mean_inv(float s, float ss) {
    __shared__ float shs[8], shq[8], outv[2];
#pragma unroll
    for (int o = 16; o > 0; o >>= 1) {
        s  += __shfl_xor_sync(0xffffffffu, s, o);
        ss += __shfl_xor_sync(0xffffffffu, ss, o);
    }
    int w = threadIdx.x >> 5;
    if ((threadIdx.x & 31) == 0) { shs[w] = s; shq[w] = ss; }
    __syncthreads();
    if (threadIdx.x == 0) {
        float ts = 0.f, tq = 0.f;
#pragma unroll
        for (int i = 0; i < 8; i++) { ts += shs[i]; tq += shq[i]; }
        float m = ts * (1.0f / ND);
        float var = tq * (1.0f / ND) - m * m;
        outv[0] = m;
        outv[1] = rsqrtf(var + LN_EPS);
    }
    __syncthreads();
    return make_float2(outv[0], outv[1]);
}

// ---------------------------------------------------------------------------
// K1: xn = LN(x)   one block per row, 256 threads, 4 floats each
// ---------------------------------------------------------------------------
__global__ __launch_bounds__(256) void ln_kernel(
    const float* __restrict__ x, const float* __restrict__ g,
    const float* __restrict__ b, float* __restrict__ out)
{
    size_t row = blockIdx.x;
    const float4* xr = (const float4*)(x + row * ND);
    float4 v = xr[threadIdx.x];
    float s = v.x + v.y + v.z + v.w;
    float ss = v.x * v.x + v.y * v.y + v.z * v.z + v.w * v.w;
    float2 mi = block_mean_inv(s, ss);
    float4 gv = ((const float4*)g)[threadIdx.x];
    float4 bv = ((const float4*)b)[threadIdx.x];
    float4 o;
    o.x = (v.x - mi.x) * mi.y * gv.x + bv.x;
    o.y = (v.y - mi.x) * mi.y * gv.y + bv.y;
    o.z = (v.z - mi.x) * mi.y * gv.z + bv.z;
    o.w = (v.w - mi.x) * mi.y * gv.w + bv.w;
    ((float4*)(out + row * ND))[threadIdx.x] = o;
}

// ---------------------------------------------------------------------------
// Conv setup: per-channel constants in double precision
// ---------------------------------------------------------------------------
__global__ void conv_setup(const float* __restrict__ ph_re,
                           const float* __restrict__ ph_im)
{
    int d = threadIdx.x;  // 1024 threads, 1 block
    double pr = (double)ph_re[d], pi = (double)ph_im[d];
    double a  = sqrt(pr * pr + pi * pi);
    double th = atan2(pi, pr);
    double r  = exp(-a);
    g_phz[d]  = make_float2((float)(r * cos(th)), (float)(r * sin(th)));
    double rT = exp(-a * (double)NT);
    double aT = (double)NT * th;
    g_phzT[d] = make_float2((float)(rT * cos(aT)), (float)(rT * sin(aT)));
    for (int j = 0; j < NC; j++) {
        double t  = (double)(j * NT + 1);
        double rj = exp(-a * t);
        double aj = t * th;
        g_Q[j * ND + d] = make_float2((float)(rj * cos(aj)), (float)(rj * sin(aj)));
    }
}

// ---------------------------------------------------------------------------
// Conv phase A: chunk-local scan end states
// grid (ND/256, NC, NB)
// ---------------------------------------------------------------------------
__global__ __launch_bounds__(256) void conv_scanA(const float* __restrict__ xn)
{
    int d = blockIdx.x * 256 + threadIdx.x;
    int j = blockIdx.y, b = blockIdx.z;
    float2 p = g_phz[d];
    float sr = 0.f, si = 0.f;
    const float* base = xn + ((size_t)b * NL + (size_t)j * NT) * ND + d;
#pragma unroll 4
    for (int i = 0; i < NT; i++) {
        float xv = base[(size_t)i * ND];
        float nr = fmaf(sr, p.x, fmaf(-si, p.y, xv));
        float ni = fmaf(sr, p.y, si * p.x);
        sr = nr; si = ni;
    }
    g_E[((size_t)b * NC + j) * ND + d] = make_float2(sr, si);
}

// ---------------------------------------------------------------------------
// Conv phase B: serial carry across chunks (B*D threads, NC steps)
// ---------------------------------------------------------------------------
__global__ __launch_bounds__(256) void conv_scanB()
{
    int idx = blockIdx.x * 256 + threadIdx.x;   // 0..NB*ND-1
    int b = idx / ND, d = idx % ND;
    float2 pT = g_phzT[d];
    float cr = 0.f, ci = 0.f;
#pragma unroll
    for (int j = 0; j < NC; j++) {
        size_t off = ((size_t)b * NC + j) * ND + d;
        g_carry[off] = make_float2(cr, ci);
        float2 e = g_E[off];
        float nr = fmaf(cr, pT.x, fmaf(-ci, pT.y, e.x));
        float ni = fmaf(cr, pT.y, fmaf(ci, pT.x, e.y));
        cr = nr; ci = ni;
    }
}

// ---------------------------------------------------------------------------
// Conv phase C: recompute with carry, emit conv.real
// ---------------------------------------------------------------------------
__global__ __launch_bounds__(256) void conv_scanC(
    const float* __restrict__ xn,
    const float* __restrict__ phi_re, const float* __restrict__ phi_im,
    const float* __restrict__ lci_re, const float* __restrict__ lci_im,
    float* __restrict__ conv)
{
    int d = blockIdx.x * 256 + threadIdx.x;
    int j = blockIdx.y, b = blockIdx.z;
    float2 p  = g_phz[d];
    float2 st = g_carry[((size_t)b * NC + j) * ND + d];
    float2 pw = g_Q[j * ND + d];            // phz^(j*T+1)
    float fre = phi_re[d], fim = phi_im[d];
    float lre = lci_re[d], lim = lci_im[d];
    const float* base = xn + ((size_t)b * NL + (size_t)j * NT) * ND + d;
    float* cbase = conv + ((size_t)b * NL + (size_t)j * NT) * ND + d;
#pragma unroll 4
    for (int i = 0; i < NT; i++) {
        float xv = base[(size_t)i * ND];
        float nr = fmaf(st.x, p.x, fmaf(-st.y, p.y, xv));
        float ni = fmaf(st.x, p.y, st.y * p.x);
        st.x = nr; st.y = ni;
        float cv = fmaf(fre, st.x, fmaf(-fim, st.y,
                   fmaf(lre, pw.x, -lim * pw.y)));
        cbase[(size_t)i * ND] = cv;
        float pr = fmaf(pw.x, p.x, -pw.y * p.y);
        float pi = fmaf(pw.x, p.y, pw.y * p.x);
        pw.x = pr; pw.y = pi;
    }
}

// ---------------------------------------------------------------------------
// K4: x2 = conv*y + x ; x3 = LN(x2)
// ---------------------------------------------------------------------------
__global__ __launch_bounds__(256) void x2_ln_kernel(
    const float* __restrict__ x, const float* __restrict__ conv,
    const float* __restrict__ y, const float* __restrict__ g,
    const float* __restrict__ b, float* __restrict__ x2,
    float* __restrict__ x3)
{
    size_t row = blockIdx.x;
    float4 xv = ((const float4*)(x + row * ND))[threadIdx.x];
    float4 cv = ((const float4*)(conv + row * ND))[threadIdx.x];
    float4 yv = ((const float4*)(y + row * ND))[threadIdx.x];
    float4 v;
    v.x = fmaf(cv.x, yv.x, xv.x);
    v.y = fmaf(cv.y, yv.y, xv.y);
    v.z = fmaf(cv.z, yv.z, xv.z);
    v.w = fmaf(cv.w, yv.w, xv.w);
    float s = v.x + v.y + v.z + v.w;
    float ss = v.x * v.x + v.y * v.y + v.z * v.z + v.w * v.w;
    float2 mi = block_mean_inv(s, ss);
    ((float4*)(x2 + row * ND))[threadIdx.x] = v;
    float4 gv = ((const float4*)g)[threadIdx.x];
    float4 bv = ((const float4*)b)[threadIdx.x];
    float4 o;
    o.x = (v.x - mi.x) * mi.y * gv.x + bv.x;
    o.y = (v.y - mi.x) * mi.y * gv.y + bv.y;
    o.z = (v.z - mi.x) * mi.y * gv.z + bv.z;
    o.w = (v.w - mi.x) * mi.y * gv.w + bv.w;
    ((float4*)(x3 + row * ND))[threadIdx.x] = o;
}

// ---------------------------------------------------------------------------
// GEMM: C[M,N] = A[M,K] @ B[K,N] (+bias[n]); EPI 0: silu, EPI 1: +add[m,n]
// 128x128x16 tile, 256 threads, 8x8 per thread
// ---------------------------------------------------------------------------
__device__ __forceinline__ float silu_f(float v) {
    return v * (1.0f / (1.0f + expf(-v)));
}

template <int EPI>
__global__ __launch_bounds__(256) void gemm128(
    const float* __restrict__ A, const float* __restrict__ Bm,
    const float* __restrict__ bias, const float* __restrict__ add,
    float* __restrict__ Cm, int M, int N, int K)
{
    constexpr int BK = 16;
    __shared__ float As[BK][132];   // [k][m], 132*4B row = 528B (16B aligned)
    __shared__ float Bs[BK][132];   // [k][n]
    int tid = threadIdx.x;
    int bm = blockIdx.y * 128;
    int bn = blockIdx.x * 128;
    int tm = (tid >> 4) * 8;
    int tn = (tid & 15) * 8;

    float acc[8][8];
#pragma unroll
    for (int i = 0; i < 8; i++)
#pragma unroll
        for (int j = 0; j < 8; j++) acc[i][j] = 0.f;

    for (int k0 = 0; k0 < K; k0 += BK) {
        // A tile: 128 rows x 16 cols -> transposed store
#pragma unroll
        for (int r = 0; r < 2; r++) {
            int f = tid + r * 256;          // 0..511 float4 slots
            int row = f >> 2;
            int kc = (f & 3) * 4;
            float4 v = *(const float4*)&A[(size_t)(bm + row) * K + k0 + kc];
            As[kc + 0][row] = v.x;
            As[kc + 1][row] = v.y;
            As[kc + 2][row] = v.z;
            As[kc + 3][row] = v.w;
        }
        // B tile: 16 rows x 128 cols, direct vectorized
#pragma unroll
        for (int r = 0; r < 2; r++) {
            int f = tid + r * 256;
            int row = f >> 5;
            int nc = (f & 31) * 4;
            *(float4*)&Bs[row][nc] =
                *(const float4*)&Bm[(size_t)(k0 + row) * N + bn + nc];
        }
        __syncthreads();
#pragma unroll
        for (int kk = 0; kk < BK; kk++) {
            float a[8], bb[8];
            *(float4*)&a[0]  = *(const float4*)&As[kk][tm];
            *(float4*)&a[4]  = *(const float4*)&As[kk][tm + 4];
            *(float4*)&bb[0] = *(const float4*)&Bs[kk][tn];
            *(float4*)&bb[4] = *(const float4*)&Bs[kk][tn + 4];
#pragma unroll
            for (int i = 0; i < 8; i++)
#pragma unroll
                for (int j = 0; j < 8; j++)
                    acc[i][j] = fmaf(a[i], bb[j], acc[i][j]);
        }
        __syncthreads();
    }

#pragma unroll
    for (int i = 0; i < 8; i++) {
        int m = bm + tm + i;
#pragma unroll
        for (int j = 0; j < 8; j++) {
            int n = bn + tn + j;
            float v = acc[i][j] + bias[n];
            if (EPI == 0) {
                v = silu_f(v);
            } else {
                v += add[(size_t)m * N + n];
            }
            Cm[(size_t)m * N + n] = v;
        }
    }
}

// ---------------------------------------------------------------------------
// Launch
// ---------------------------------------------------------------------------
extern "C" void kernel_launch(void* const* d_in, const int* in_sizes, int n_in,
                              void* d_out, int out_size)
{
    const float* x      = (const float*)d_in[0];
    const float* ln_g   = (const float*)d_in[1];
    const float* ln_b   = (const float*)d_in[2];
    const float* fc_w   = (const float*)d_in[3];
    const float* fc_b   = (const float*)d_in[4];
    const float* w1     = (const float*)d_in[5];
    const float* b1     = (const float*)d_in[6];
    const float* w2     = (const float*)d_in[7];
    const float* b2     = (const float*)d_in[8];
    const float* ph_re  = (const float*)d_in[9];
    const float* ph_im  = (const float*)d_in[10];
    const float* phi_re = (const float*)d_in[11];
    const float* phi_im = (const float*)d_in[12];
    const float* lci_re = (const float*)d_in[13];
    const float* lci_im = (const float*)d_in[14];
    float* out = (float*)d_out;

    float *xn, *conv, *y, *x2, *x3, *t1;
    cudaGetSymbolAddress((void**)&xn,   g_xn);
    cudaGetSymbolAddress((void**)&conv, g_conv);
    cudaGetSymbolAddress((void**)&y,    g_y);
    cudaGetSymbolAddress((void**)&x2,   g_x2);
    cudaGetSymbolAddress((void**)&x3,   g_x3);
    cudaGetSymbolAddress((void**)&t1,   g_t1);

    // 1) xn = LN(x)
    ln_kernel<<<NM, 256>>>(x, ln_g, ln_b, xn);
    // 2) conv constants
    conv_setup<<<1, ND>>>(ph_re, ph_im);
    // 3-5) chunked scan
    dim3 gs(ND / 256, NC, NB);
    conv_scanA<<<gs, 256>>>(xn);
    conv_scanB<<<(NB * ND) / 256, 256>>>();
    conv_scanC<<<gs, 256>>>(xn, phi_re, phi_im, lci_re, lci_im, conv);
    // 6) y = silu(x @ fc_w + fc_b)
    gemm128<0><<<dim3(ND / 128, NM / 128), 256>>>(x, fc_w, fc_b, nullptr, y,
                                                  NM, ND, ND);
    // 7) x2 = conv*y + x ; x3 = LN(x2)
    x2_ln_kernel<<<NM, 256>>>(x, conv, y, ln_g, ln_b, x2, x3);
    // 8) t1 = silu(x3 @ w1 + b1)
    gemm128<0><<<dim3(NFF / 128, NM / 128), 256>>>(x3, w1, b1, nullptr, t1,
                                                   NM, NFF, ND);
    // 9) out = x2 + t1 @ w2 + b2
    gemm128<1><<<dim3(ND / 128, NM / 128), 256>>>(t1, w2, b2, x2, out,
                                                  NM, ND, NFF);
}

// round 9
// speedup vs baseline: 2.9767x; 2.9767x over previous
#include <cuda_runtime.h>
#include <cuda_bf16.h>
#include <math.h>
#include <stdint.h>

// Problem dims (fixed by the reference)
#define NB 4
#define NL 4096
#define ND 1024
#define NFF 2048
#define NM (NB * NL)          // 16384 rows
#define NT 128                // conv chunk length
#define NC (NL / NT)          // 32 chunks
#define LN_EPS 1e-5f

// GEMM tiling (shared by both paths: grid is dim3(N/NTG, M/MT))
#define MT 128                // M tile per CTA
#define NTG 256               // N tile per CTA
#define KC 64                 // tcgen05 K chunk (bf16) = 128B SW128 row
#define GEMM_SMEM (1024 + 2 * 98304)   // 193 KB (covers both paths)

// Arch-feature dispatch: tcgen05 only exists on *a targets.
#if defined(__CUDA_ARCH_FEAT_SM103_ALL) || defined(__CUDA_ARCH_FEAT_SM100_ALL) || \
    defined(__CUDA_ARCH_FEAT_SM101_ALL) || defined(__CUDA_ARCH_FEAT_SM110_ALL)
#define USE_TC05 1
#else
#define USE_TC05 0
#endif

// ---------------------------------------------------------------------------
// Static scratch (no cudaMalloc allowed)
// ---------------------------------------------------------------------------
__device__ float g_xn[NM * ND];     // LN(x)
__device__ float g_conv[NM * ND];   // spiral conv (real part)
__device__ float g_y[NM * ND];      // silu(x@fc_w + fc_b)
__device__ float g_x2[NM * ND];     // c*y + x

__device__ __nv_bfloat16 g_xh[NM * ND],  g_xl[NM * ND];     // x split
__device__ __nv_bfloat16 g_x3h[NM * ND], g_x3l[NM * ND];    // LN(x2) split
__device__ __nv_bfloat16 g_t1h[NM * NFF], g_t1l[NM * NFF];  // silu(x3@w1+b1) split
__device__ __nv_bfloat16 g_fcTh[ND * ND],  g_fcTl[ND * ND];   // fc_w^T split [N,K]
__device__ __nv_bfloat16 g_w1Th[NFF * ND], g_w1Tl[NFF * ND];  // w1^T  [2048,1024]
__device__ __nv_bfloat16 g_w2Th[ND * NFF], g_w2Tl[ND * NFF];  // w2^T  [1024,2048]

__device__ float2 g_E[NB * NC * ND];      // chunk-local end states
__device__ float2 g_carry[NB * NC * ND];  // incoming state per chunk
__device__ float2 g_phz[ND];              // phz
__device__ float2 g_phzT[ND];             // phz^T
__device__ float2 g_Q[NC * ND];           // phz^(j*T + 1)

// ---------------------------------------------------------------------------
// PTX helpers
// ---------------------------------------------------------------------------
__device__ __forceinline__ uint32_t smem_u32(const void* p) {
    uint32_t a;
    asm("{ .reg .u64 t; cvta.to.shared.u64 t, %1; cvt.u32.u64 %0, t; }"
        : "=r"(a) : "l"(p));
    return a;
}
__device__ __forceinline__ void cpa16(uint32_t dst, const void* src) {
    asm volatile("cp.async.cg.shared.global [%0], [%1], 16;" :: "r"(dst), "l"(src));
}

#define LDSM4(r, a) \
    asm volatile("ldmatrix.sync.aligned.m8n8.x4.shared.b16 {%0,%1,%2,%3}, [%4];" \
        : "=r"((r)[0]), "=r"((r)[1]), "=r"((r)[2]), "=r"((r)[3]) : "r"(a))

#define FB_MMA(c, a, b0v, b1v) \
    asm volatile("mma.sync.aligned.m16n8k16.row.col.f32.bf16.bf16.f32 " \
        "{%0,%1,%2,%3}, {%4,%5,%6,%7}, {%8,%9}, {%0,%1,%2,%3};" \
        : "+f"((c)[0]), "+f"((c)[1]), "+f"((c)[2]), "+f"((c)[3]) \
        : "r"((a)[0]), "r"((a)[1]), "r"((a)[2]), "r"((a)[3]), "r"(b0v), "r"(b1v))

#if USE_TC05
__device__ __forceinline__ uint32_t elect_one_pred() {
    uint32_t pred;
    asm volatile(
        "{\n\t.reg .pred p;\n\telect.sync _|p, 0xFFFFFFFF;\n\t"
        "selp.b32 %0, 1, 0, p;\n\t}" : "=r"(pred));
    return pred;
}
#define MBAR_INIT(addr, cnt) \
    asm volatile("mbarrier.init.shared.b64 [%0], %1;" :: "r"(addr), "r"(cnt) : "memory")
#define MBAR_WAIT(addr, par) do {                                             \
    uint32_t _m = (addr); uint32_t _p = (par); uint32_t _d;                   \
    asm volatile("{\n\t.reg .pred p;\n\t"                                     \
        "mbarrier.try_wait.parity.acquire.cta.shared::cta.b64 p, [%1], %2;\n\t" \
        "selp.b32 %0, 1, 0, p;\n\t}" : "=r"(_d) : "r"(_m), "r"(_p) : "memory"); \
    if (!_d) {                                                                \
        asm volatile("{\n\t.reg .pred P1;\n\t"                                \
            "WL_%=:\n\t"                                                      \
            "mbarrier.try_wait.parity.acquire.cta.shared::cta.b64 P1, [%0], %1, 0x989680;\n\t" \
            "@P1 bra.uni WD_%=;\n\tbra.uni WL_%=;\n\tWD_%=:\n\t}"             \
            :: "r"(_m), "r"(_p) : "memory");                                  \
    } } while (0)
#define TC_ALLOC(saddr, n) \
    asm volatile("tcgen05.alloc.cta_group::1.sync.aligned.shared::cta.b32 [%0], %1;" \
                 :: "r"(saddr), "r"((uint32_t)(n)) : "memory")
#define TC_RELINQ() \
    asm volatile("tcgen05.relinquish_alloc_permit.cta_group::1.sync.aligned;")
#define TC_DEALLOC(t, n) \
    asm volatile("tcgen05.dealloc.cta_group::1.sync.aligned.b32 %0, %1;" \
                 :: "r"(t), "r"((uint32_t)(n)))
#define TC_COMMIT(mb) \
    asm volatile("tcgen05.commit.cta_group::1.mbarrier::arrive::one.shared::cluster.b64 [%0];" \
                 :: "r"(mb) : "memory")
#define TC_FENCE_AFTER()  asm volatile("tcgen05.fence::after_thread_sync;" ::: "memory")
#define TC_FENCE_BEFORE() asm volatile("tcgen05.fence::before_thread_sync;" ::: "memory")
#define TC_WAIT_LD()      asm volatile("tcgen05.wait::ld.sync.aligned;" ::: "memory")
#define TC_LD_X32(r, ta) \
    asm volatile("tcgen05.ld.sync.aligned.32x32b.x32.b32 " \
        "{%0,%1,%2,%3,%4,%5,%6,%7,%8,%9,%10,%11,%12,%13,%14,%15," \
        "%16,%17,%18,%19,%20,%21,%22,%23,%24,%25,%26,%27,%28,%29,%30,%31}, [%32];" \
        : "=r"((r)[0]),"=r"((r)[1]),"=r"((r)[2]),"=r"((r)[3]),               \
          "=r"((r)[4]),"=r"((r)[5]),"=r"((r)[6]),"=r"((r)[7]),               \
          "=r"((r)[8]),"=r"((r)[9]),"=r"((r)[10]),"=r"((r)[11]),             \
          "=r"((r)[12]),"=r"((r)[13]),"=r"((r)[14]),"=r"((r)[15]),           \
          "=r"((r)[16]),"=r"((r)[17]),"=r"((r)[18]),"=r"((r)[19]),           \
          "=r"((r)[20]),"=r"((r)[21]),"=r"((r)[22]),"=r"((r)[23]),           \
          "=r"((r)[24]),"=r"((r)[25]),"=r"((r)[26]),"=r"((r)[27]),           \
          "=r"((r)[28]),"=r"((r)[29]),"=r"((r)[30]),"=r"((r)[31])            \
        : "r"(ta))

static constexpr uint64_t DESC_BASE_SW128 =
    (uint64_t(2) << 61) | (uint64_t(1) << 46) | (uint64_t(64) << 32) | (uint64_t(1) << 16);
#define MK_DESC(a) (DESC_BASE_SW128 | ((uint64_t)((a) >> 4) & 0x3FFF))
__device__ __forceinline__ uint32_t sw128(uint32_t o) { return o ^ ((o >> 3) & 0x70); }
__device__ __forceinline__ void mma_f16_ss(uint32_t d, uint64_t ad, uint64_t bd,
                                           uint32_t idesc, uint32_t en) {
    asm volatile(
        "{\n\t.reg .pred p;\n\tsetp.ne.u32 p, %5, 0;\n\t"
        "tcgen05.mma.cta_group::1.kind::f16 [%0], %1, %2, %3, {%4,%4,%4,%4}, p;\n\t}"
        :: "r"(d), "l"(ad), "l"(bd), "r"(idesc), "r"(0u), "r"(en) : "memory");
}
#endif  // USE_TC05

// ---------------------------------------------------------------------------
// LayerNorm helpers
// ---------------------------------------------------------------------------
__device__ __forceinline__ float2 block_mean_inv(float s, float ss) {
    __shared__ float shs[8], shq[8], outv[2];
#pragma unroll
    for (int o = 16; o > 0; o >>= 1) {
        s  += __shfl_xor_sync(0xffffffffu, s, o);
        ss += __shfl_xor_sync(0xffffffffu, ss, o);
    }
    int w = threadIdx.x >> 5;
    if ((threadIdx.x & 31) == 0) { shs[w] = s; shq[w] = ss; }
    __syncthreads();
    if (threadIdx.x == 0) {
        float ts = 0.f, tq = 0.f;
#pragma unroll
        for (int i = 0; i < 8; i++) { ts += shs[i]; tq += shq[i]; }
        float m = ts * (1.0f / ND);
        float var = tq * (1.0f / ND) - m * m;
        outv[0] = m;
        outv[1] = rsqrtf(var + LN_EPS);
    }
    __syncthreads();
    return make_float2(outv[0], outv[1]);
}

__global__ __launch_bounds__(256) void ln_kernel(
    const float* __restrict__ x, const float* __restrict__ g,
    const float* __restrict__ b, float* __restrict__ out)
{
    size_t row = blockIdx.x;
    float4 v = ((const float4*)(x + row * ND))[threadIdx.x];
    float s = v.x + v.y + v.z + v.w;
    float ss = v.x * v.x + v.y * v.y + v.z * v.z + v.w * v.w;
    float2 mi = block_mean_inv(s, ss);
    float4 gv = ((const float4*)g)[threadIdx.x];
    float4 bv = ((const float4*)b)[threadIdx.x];
    float4 o;
    o.x = (v.x - mi.x) * mi.y * gv.x + bv.x;
    o.y = (v.y - mi.x) * mi.y * gv.y + bv.y;
    o.z = (v.z - mi.x) * mi.y * gv.z + bv.z;
    o.w = (v.w - mi.x) * mi.y * gv.w + bv.w;
    ((float4*)(out + row * ND))[threadIdx.x] = o;
}

// ---------------------------------------------------------------------------
// Spiral conv (chunked linear recurrence)
// ---------------------------------------------------------------------------
__global__ void conv_setup(const float* __restrict__ ph_re,
                           const float* __restrict__ ph_im)
{
    int d = threadIdx.x;
    double pr = (double)ph_re[d], pi = (double)ph_im[d];
    double a  = sqrt(pr * pr + pi * pi);
    double th = atan2(pi, pr);
    double r  = exp(-a);
    g_phz[d]  = make_float2((float)(r * cos(th)), (float)(r * sin(th)));
    double rT = exp(-a * (double)NT);
    double aT = (double)NT * th;
    g_phzT[d] = make_float2((float)(rT * cos(aT)), (float)(rT * sin(aT)));
    for (int j = 0; j < NC; j++) {
        double t  = (double)(j * NT + 1);
        double rj = exp(-a * t);
        double aj = t * th;
        g_Q[j * ND + d] = make_float2((float)(rj * cos(aj)), (float)(rj * sin(aj)));
    }
}

__global__ __launch_bounds__(256) void conv_scanA(const float* __restrict__ xn)
{
    int d = blockIdx.x * 256 + threadIdx.x;
    int j = blockIdx.y, b = blockIdx.z;
    float2 p = g_phz[d];
    float sr = 0.f, si = 0.f;
    const float* base = xn + ((size_t)b * NL + (size_t)j * NT) * ND + d;
#pragma unroll 4
    for (int i = 0; i < NT; i++) {
        float xv = base[(size_t)i * ND];
        float nr = fmaf(sr, p.x, fmaf(-si, p.y, xv));
        float ni = fmaf(sr, p.y, si * p.x);
        sr = nr; si = ni;
    }
    g_E[((size_t)b * NC + j) * ND + d] = make_float2(sr, si);
}

__global__ __launch_bounds__(256) void conv_scanB()
{
    int idx = blockIdx.x * 256 + threadIdx.x;
    int b = idx / ND, d = idx % ND;
    float2 pT = g_phzT[d];
    float cr = 0.f, ci = 0.f;
#pragma unroll
    for (int j = 0; j < NC; j++) {
        size_t off = ((size_t)b * NC + j) * ND + d;
        g_carry[off] = make_float2(cr, ci);
        float2 e = g_E[off];
        float nr = fmaf(cr, pT.x, fmaf(-ci, pT.y, e.x));
        float ni = fmaf(cr, pT.y, fmaf(ci, pT.x, e.y));
        cr = nr; ci = ni;
    }
}

__global__ __launch_bounds__(256) void conv_scanC(
    const float* __restrict__ xn,
    const float* __restrict__ phi_re, const float* __restrict__ phi_im,
    const float* __restrict__ lci_re, const float* __restrict__ lci_im,
    float* __restrict__ conv)
{
    int d = blockIdx.x * 256 + threadIdx.x;
    int j = blockIdx.y, b = blockIdx.z;
    float2 p  = g_phz[d];
    float2 st = g_carry[((size_t)b * NC + j) * ND + d];
    float2 pw = g_Q[j * ND + d];
    float fre = phi_re[d], fim = phi_im[d];
    float lre = lci_re[d], lim = lci_im[d];
    const float* base = xn + ((size_t)b * NL + (size_t)j * NT) * ND + d;
    float* cbase = conv + ((size_t)b * NL + (size_t)j * NT) * ND + d;
#pragma unroll 4
    for (int i = 0; i < NT; i++) {
        float xv = base[(size_t)i * ND];
        float nr = fmaf(st.x, p.x, fmaf(-st.y, p.y, xv));
        float ni = fmaf(st.x, p.y, st.y * p.x);
        st.x = nr; st.y = ni;
        float cv = fmaf(fre, st.x, fmaf(-fim, st.y,
                   fmaf(lre, pw.x, -lim * pw.y)));
        cbase[(size_t)i * ND] = cv;
        float pr = fmaf(pw.x, p.x, -pw.y * p.y);
        float pi = fmaf(pw.x, p.y, pw.y * p.x);
        pw.x = pr; pw.y = pi;
    }
}

// ---------------------------------------------------------------------------
// bf16 hi/lo split helpers + conversion kernels
// ---------------------------------------------------------------------------
union BF4 { __nv_bfloat16 b[4]; uint2 u; };
union BF2 { __nv_bfloat16 b[2]; uint32_t u; };

__device__ __forceinline__ void split_bf16(float v, __nv_bfloat16& h, __nv_bfloat16& l) {
    h = __float2bfloat16_rn(v);
    l = __float2bfloat16_rn(v - __bfloat162float(h));
}

__global__ __launch_bounds__(256) void convert_x(
    const float* __restrict__ x, __nv_bfloat16* __restrict__ xh,
    __nv_bfloat16* __restrict__ xl)
{
    size_t i = (size_t)blockIdx.x * 256 + threadIdx.x;   // float4 index
    float4 v = ((const float4*)x)[i];
    BF4 h, l;
    split_bf16(v.x, h.b[0], l.b[0]);
    split_bf16(v.y, h.b[1], l.b[1]);
    split_bf16(v.z, h.b[2], l.b[2]);
    split_bf16(v.w, h.b[3], l.b[3]);
    ((uint2*)xh)[i] = h.u;
    ((uint2*)xl)[i] = l.u;
}

// W[K,N] f32 -> Wh,Wl [N,K] bf16 (transpose + split)
__global__ __launch_bounds__(256) void transpose_split(
    const float* __restrict__ W, __nv_bfloat16* __restrict__ Th,
    __nv_bfloat16* __restrict__ Tl, int K, int N)
{
    __shared__ float tile[32][33];
    int tx = threadIdx.x & 31, ty = threadIdx.x >> 5;   // 32 x 8
    int k0 = blockIdx.y * 32, n0 = blockIdx.x * 32;
#pragma unroll
    for (int i = 0; i < 4; i++)
        tile[ty + i * 8][tx] = W[(size_t)(k0 + ty + i * 8) * N + n0 + tx];
    __syncthreads();
#pragma unroll
    for (int i = 0; i < 4; i++) {
        float v = tile[tx][ty + i * 8];
        __nv_bfloat16 h, l;
        split_bf16(v, h, l);
        size_t off = (size_t)(n0 + ty + i * 8) * K + k0 + tx;
        Th[off] = h;
        Tl[off] = l;
    }
}

// x2 = conv*y + x ; x3 = LN(x2) -> bf16 split
__global__ __launch_bounds__(256) void x2_ln_kernel(
    const float* __restrict__ x, const float* __restrict__ conv,
    const float* __restrict__ y, const float* __restrict__ g,
    const float* __restrict__ b, float* __restrict__ x2,
    __nv_bfloat16* __restrict__ x3h, __nv_bfloat16* __restrict__ x3l)
{
    size_t row = blockIdx.x;
    float4 xv = ((const float4*)(x + row * ND))[threadIdx.x];
    float4 cv = ((const float4*)(conv + row * ND))[threadIdx.x];
    float4 yv = ((const float4*)(y + row * ND))[threadIdx.x];
    float4 v;
    v.x = fmaf(cv.x, yv.x, xv.x);
    v.y = fmaf(cv.y, yv.y, xv.y);
    v.z = fmaf(cv.z, yv.z, xv.z);
    v.w = fmaf(cv.w, yv.w, xv.w);
    float s = v.x + v.y + v.z + v.w;
    float ss = v.x * v.x + v.y * v.y + v.z * v.z + v.w * v.w;
    float2 mi = block_mean_inv(s, ss);
    ((float4*)(x2 + row * ND))[threadIdx.x] = v;
    float4 gv = ((const float4*)g)[threadIdx.x];
    float4 bv = ((const float4*)b)[threadIdx.x];
    float4 o;
    o.x = (v.x - mi.x) * mi.y * gv.x + bv.x;
    o.y = (v.y - mi.x) * mi.y * gv.y + bv.y;
    o.z = (v.z - mi.x) * mi.y * gv.z + bv.z;
    o.w = (v.w - mi.x) * mi.y * gv.w + bv.w;
    BF4 h, l;
    split_bf16(o.x, h.b[0], l.b[0]);
    split_bf16(o.y, h.b[1], l.b[1]);
    split_bf16(o.z, h.b[2], l.b[2]);
    split_bf16(o.w, h.b[3], l.b[3]);
    size_t fi = row * (ND / 4) + threadIdx.x;
    ((uint2*)x3h)[fi] = h.u;
    ((uint2*)x3l)[fi] = l.u;
}

// ---------------------------------------------------------------------------
// GEMM: C[M,N] = A[M,K] @ B^T[N,K]  (A,B as bf16 hi/lo pairs; 3-term split)
// EPI 0: Cf = silu(v+bias)            (f32)
// EPI 1: Ch/Cl = split(silu(v+bias))  (bf16 pair)
// EPI 2: Cf = v + bias + add          (f32)
// Two implementations, chosen at device-compile time:
//   - sm_10xa: tcgen05 SS MMA, 2-stage cp.async pipeline, 128x256 tile
//   - base sm_103: mma.sync m16n8k16 bf16, 3-stage cp.async, same 128x256 tile
// ---------------------------------------------------------------------------
__device__ __forceinline__ float silu_f(float v) {
    return v * (1.0f / (1.0f + expf(-v)));
}

template <int EPI>
__global__ __launch_bounds__(256) void gemm_tc(
    const __nv_bfloat16* __restrict__ Ah, const __nv_bfloat16* __restrict__ Al,
    const __nv_bfloat16* __restrict__ Bh, const __nv_bfloat16* __restrict__ Bl,
    const float* __restrict__ bias, const float* __restrict__ add,
    float* __restrict__ Cf, __nv_bfloat16* __restrict__ Ch,
    __nv_bfloat16* __restrict__ Cl, int M, int N, int K)
{
#if USE_TC05
    // ======================= tcgen05 path (sm_103a) ========================
    extern __shared__ char smem[];
    uint32_t sb = smem_u32(smem);
    const int tid = threadIdx.x, wid = tid >> 5, lid = tid & 31;
    const int bm = blockIdx.y * MT;
    const int bn = blockIdx.x * NTG;

    const uint32_t ST0 = 1024, STS = 98304;
    const uint32_t OFF_AH = 0, OFF_AL = 16384, OFF_BH = 32768, OFF_BL = 65536;

    if (wid == 0) { TC_ALLOC(sb, 256); TC_RELINQ(); }
    if (tid == 0) { MBAR_INIT(sb + 16, 1); MBAR_INIT(sb + 24, 1); }
    __syncthreads();
    uint32_t tmem;
    asm volatile("ld.shared.b32 %0,[%1];" : "=r"(tmem) : "r"(sb));

    const int nk = K / KC;

    auto load_chunk = [&](int j) {
        uint32_t stg = sb + ST0 + (uint32_t)(j & 1) * STS;
        int k0 = j * KC;
#pragma unroll
        for (int it = 0; it < 4; it++) {
            int slot = tid + it * 256;
            int r = slot >> 3, g = slot & 7;
            uint32_t so = sw128((uint32_t)(r * 128 + g * 16));
            const size_t go = (size_t)(bm + r) * K + k0 + g * 8;
            cpa16(stg + OFF_AH + so, Ah + go);
            cpa16(stg + OFF_AL + so, Al + go);
        }
#pragma unroll
        for (int it = 0; it < 8; it++) {
            int slot = tid + it * 256;
            int r = slot >> 3, g = slot & 7;
            uint32_t so = sw128((uint32_t)(r * 128 + g * 16));
            const size_t go = (size_t)(bn + r) * K + k0 + g * 8;
            cpa16(stg + OFF_BH + so, Bh + go);
            cpa16(stg + OFF_BL + so, Bl + go);
        }
        asm volatile("cp.async.commit_group;" ::: "memory");
    };

    load_chunk(0);
    const uint32_t idesc = (1u << 4) | (1u << 7) | (1u << 10) |
                           ((NTG / 8) << 17) | ((MT / 16) << 24);

    for (int i = 0; i < nk; i++) {
        asm volatile("cp.async.wait_group 0;" ::: "memory");
        asm volatile("fence.proxy.async.shared::cta;" ::: "memory");
        __syncthreads();
        uint32_t stg = sb + ST0 + (uint32_t)(i & 1) * STS;
        if (wid == 0 && elect_one_pred()) {
            uint64_t dah = MK_DESC(stg + OFF_AH);
            uint64_t dal = MK_DESC(stg + OFF_AL);
            uint64_t dbh = MK_DESC(stg + OFF_BH);
            uint64_t dbl = MK_DESC(stg + OFF_BL);
#pragma unroll
            for (int ks = 0; ks < 4; ks++) {
                mma_f16_ss(tmem, dah + ks * 2, dbh + ks * 2, idesc,
                           (i == 0 && ks == 0) ? 0u : 1u);
                mma_f16_ss(tmem, dah + ks * 2, dbl + ks * 2, idesc, 1u);
                mma_f16_ss(tmem, dal + ks * 2, dbh + ks * 2, idesc, 1u);
            }
            TC_COMMIT(sb + 16 + (uint32_t)(i & 1) * 8);
        }
        int j = i + 1;
        if (j < nk) {
            if (j >= 2)
                MBAR_WAIT(sb + 16 + (uint32_t)(j & 1) * 8, ((j - 2) >> 1) & 1);
            load_chunk(j);
        }
    }

    MBAR_WAIT(sb + 16 + (uint32_t)((nk - 1) & 1) * 8, ((nk - 1) >> 1) & 1);
    TC_FENCE_AFTER();

    const int m = bm + (wid & 3) * 32 + lid;
    const int chalf = (wid >> 2) * 128;
#pragma unroll
    for (int cc = 0; cc < 4; cc++) {
        int col = chalf + cc * 32;
        uint32_t r[32];
        TC_LD_X32(r, tmem + col);
        TC_WAIT_LD();
        int nbase = bn + col;
        const float4* bp = (const float4*)&bias[nbase];
        if (EPI == 0) {
            float* dst = Cf + (size_t)m * N + nbase;
#pragma unroll
            for (int q = 0; q < 8; q++) {
                float4 bv = bp[q];
                float4 o;
                o.x = silu_f(__uint_as_float(r[4 * q + 0]) + bv.x);
                o.y = silu_f(__uint_as_float(r[4 * q + 1]) + bv.y);
                o.z = silu_f(__uint_as_float(r[4 * q + 2]) + bv.z);
                o.w = silu_f(__uint_as_float(r[4 * q + 3]) + bv.w);
                ((float4*)dst)[q] = o;
            }
        } else if (EPI == 1) {
            __nv_bfloat16* dh = Ch + (size_t)m * N + nbase;
            __nv_bfloat16* dl = Cl + (size_t)m * N + nbase;
#pragma unroll
            for (int q = 0; q < 8; q++) {
                float4 bv = bp[q];
                BF4 h, l;
                float v0 = silu_f(__uint_as_float(r[4 * q + 0]) + bv.x);
                float v1 = silu_f(__uint_as_float(r[4 * q + 1]) + bv.y);
                float v2 = silu_f(__uint_as_float(r[4 * q + 2]) + bv.z);
                float v3 = silu_f(__uint_as_float(r[4 * q + 3]) + bv.w);
                split_bf16(v0, h.b[0], l.b[0]);
                split_bf16(v1, h.b[1], l.b[1]);
                split_bf16(v2, h.b[2], l.b[2]);
                split_bf16(v3, h.b[3], l.b[3]);
                ((uint2*)dh)[q] = h.u;
                ((uint2*)dl)[q] = l.u;
            }
        } else {
            const float4* ap = (const float4*)&add[(size_t)m * N + nbase];
            float* dst = Cf + (size_t)m * N + nbase;
#pragma unroll
            for (int q = 0; q < 8; q++) {
                float4 bv = bp[q];
                float4 av = ap[q];
                float4 o;
                o.x = __uint_as_float(r[4 * q + 0]) + bv.x + av.x;
                o.y = __uint_as_float(r[4 * q + 1]) + bv.y + av.y;
                o.z = __uint_as_float(r[4 * q + 2]) + bv.z + av.z;
                o.w = __uint_as_float(r[4 * q + 3]) + bv.w + av.w;
                ((float4*)dst)[q] = o;
            }
        }
    }
    TC_FENCE_BEFORE();
    __syncthreads();
    if (wid == 0) TC_DEALLOC(tmem, 256);

#else
    // =================== mma.sync fallback (base sm_103) ===================
    // CTA tile 128x256, K-chunk 32, 3-stage cp.async pipeline.
    // Warp grid 2(m) x 4(n); warp tile 64x64; m16n8k16 bf16 HMMA.
    // SMEM stage layout (rows padded to 80B for conflict-free ldmatrix):
    //   sAh: [128][40]bf16 @ 0        (10240 B)
    //   sAl:               @ 10240
    //   sBh: [256][40]bf16 @ 20480    (20480 B)
    //   sBl:               @ 40960
    //   stage bytes: 61440; 3 stages = 184320 B
    extern __shared__ char smem[];
    uint32_t sb = smem_u32(smem);
    const int tid = threadIdx.x, wid = tid >> 5, lid = tid & 31;
    const int bm = blockIdx.y * MT;
    const int bn = blockIdx.x * NTG;
    const int wm = wid >> 2, wn = wid & 3;
    const uint32_t STGB = 61440u;

    const int nk = K / 32;

    auto fb_load = [&](int j) {
        uint32_t stg = sb + (uint32_t)(j % 3) * STGB;
        int k0 = j * 32;
#pragma unroll
        for (int t = 0; t < 2; t++) {
            int slot = tid + t * 256;              // 0..511
            int row = slot >> 2, c = slot & 3;
            uint32_t so = (uint32_t)(row * 80 + c * 16);
            size_t go = (size_t)(bm + row) * K + k0 + c * 8;
            cpa16(stg + so,          Ah + go);
            cpa16(stg + 10240u + so, Al + go);
        }
#pragma unroll
        for (int t = 0; t < 4; t++) {
            int slot = tid + t * 256;              // 0..1023
            int row = slot >> 2, c = slot & 3;
            uint32_t so = (uint32_t)(row * 80 + c * 16);
            size_t go = (size_t)(bn + row) * K + k0 + c * 8;
            cpa16(stg + 20480u + so, Bh + go);
            cpa16(stg + 40960u + so, Bl + go);
        }
        asm volatile("cp.async.commit_group;" ::: "memory");
    };

    float acc[4][8][4];
#pragma unroll
    for (int a = 0; a < 4; a++)
#pragma unroll
        for (int b = 0; b < 8; b++)
#pragma unroll
            for (int c = 0; c < 4; c++) acc[a][b][c] = 0.f;

    fb_load(0);
    fb_load(1);

    const int r8 = lid & 7, g8 = lid >> 3;

    for (int i = 0; i < nk; i++) {
        if (i + 1 < nk)
            asm volatile("cp.async.wait_group 1;" ::: "memory");
        else
            asm volatile("cp.async.wait_group 0;" ::: "memory");
        __syncthreads();
        uint32_t stg = sb + (uint32_t)(i % 3) * STGB;
#pragma unroll
        for (int ks = 0; ks < 2; ks++) {
            int kb = ks * 16;
            uint32_t ah[4][4], al[4][4];
#pragma unroll
            for (int mi = 0; mi < 4; mi++) {
                int row = wm * 64 + mi * 16 + (g8 & 1) * 8 + r8;
                int ko = (g8 >> 1) * 8 + kb;
                uint32_t ad = stg + (uint32_t)(row * 80 + ko * 2);
                LDSM4(ah[mi], ad);
                LDSM4(al[mi], ad + 10240u);
            }
#pragma unroll
            for (int half = 0; half < 4; half++) {
                uint32_t bh[4], bl[4];
                int row = wn * 64 + half * 16 + (g8 >> 1) * 8 + r8;
                int ko = (g8 & 1) * 8 + kb;
                uint32_t bd = stg + 20480u + (uint32_t)(row * 80 + ko * 2);
                LDSM4(bh, bd);
                LDSM4(bl, bd + 20480u);
#pragma unroll
                for (int mi = 0; mi < 4; mi++) {
                    FB_MMA(acc[mi][2 * half],     ah[mi], bh[0], bh[1]);
                    FB_MMA(acc[mi][2 * half],     ah[mi], bl[0], bl[1]);
                    FB_MMA(acc[mi][2 * half],     al[mi], bh[0], bh[1]);
                    FB_MMA(acc[mi][2 * half + 1], ah[mi], bh[2], bh[3]);
                    FB_MMA(acc[mi][2 * half + 1], ah[mi], bl[2], bl[3]);
                    FB_MMA(acc[mi][2 * half + 1], al[mi], bh[2], bh[3]);
                }
            }
        }
        if (i + 2 < nk) fb_load(i + 2);
    }

    // Epilogue: thread holds (m0, m0+8) x (n, n+1) per (mi, ni)
#pragma unroll
    for (int mi = 0; mi < 4; mi++) {
        int m0 = bm + wm * 64 + mi * 16 + (lid >> 2);
#pragma unroll
        for (int rr = 0; rr < 2; rr++) {
            int m = m0 + rr * 8;
#pragma unroll
            for (int ni = 0; ni < 8; ni++) {
                int n = bn + wn * 64 + ni * 8 + (lid & 3) * 2;
                float c0 = acc[mi][ni][2 * rr + 0];
                float c1 = acc[mi][ni][2 * rr + 1];
                float2 bv = *(const float2*)&bias[n];
                float v0 = c0 + bv.x, v1 = c1 + bv.y;
                if (EPI == 0) {
                    float2 o = make_float2(silu_f(v0), silu_f(v1));
                    *(float2*)&Cf[(size_t)m * N + n] = o;
                } else if (EPI == 1) {
                    v0 = silu_f(v0); v1 = silu_f(v1);
                    BF2 h, l;
                    split_bf16(v0, h.b[0], l.b[0]);
                    split_bf16(v1, h.b[1], l.b[1]);
                    *(uint32_t*)&Ch[(size_t)m * N + n] = h.u;
                    *(uint32_t*)&Cl[(size_t)m * N + n] = l.u;
                } else {
                    float2 av = *(const float2*)&add[(size_t)m * N + n];
                    float2 o = make_float2(v0 + av.x, v1 + av.y);
                    *(float2*)&Cf[(size_t)m * N + n] = o;
                }
            }
        }
    }
#endif  // USE_TC05
}

// ---------------------------------------------------------------------------
// Launch
// ---------------------------------------------------------------------------
extern "C" void kernel_launch(void* const* d_in, const int* in_sizes, int n_in,
                              void* d_out, int out_size)
{
    const float* x      = (const float*)d_in[0];
    const float* ln_g   = (const float*)d_in[1];
    const float* ln_b   = (const float*)d_in[2];
    const float* fc_w   = (const float*)d_in[3];
    const float* fc_b   = (const float*)d_in[4];
    const float* w1     = (const float*)d_in[5];
    const float* b1     = (const float*)d_in[6];
    const float* w2     = (const float*)d_in[7];
    const float* b2     = (const float*)d_in[8];
    const float* ph_re  = (const float*)d_in[9];
    const float* ph_im  = (const float*)d_in[10];
    const float* phi_re = (const float*)d_in[11];
    const float* phi_im = (const float*)d_in[12];
    const float* lci_re = (const float*)d_in[13];
    const float* lci_im = (const float*)d_in[14];
    float* out = (float*)d_out;

    float *xn, *conv, *y, *x2;
    __nv_bfloat16 *xh, *xl, *x3h, *x3l, *t1h, *t1l;
    __nv_bfloat16 *fcTh, *fcTl, *w1Th, *w1Tl, *w2Th, *w2Tl;
    cudaGetSymbolAddress((void**)&xn,   g_xn);
    cudaGetSymbolAddress((void**)&conv, g_conv);
    cudaGetSymbolAddress((void**)&y,    g_y);
    cudaGetSymbolAddress((void**)&x2,   g_x2);
    cudaGetSymbolAddress((void**)&xh,   g_xh);
    cudaGetSymbolAddress((void**)&xl,   g_xl);
    cudaGetSymbolAddress((void**)&x3h,  g_x3h);
    cudaGetSymbolAddress((void**)&x3l,  g_x3l);
    cudaGetSymbolAddress((void**)&t1h,  g_t1h);
    cudaGetSymbolAddress((void**)&t1l,  g_t1l);
    cudaGetSymbolAddress((void**)&fcTh, g_fcTh);
    cudaGetSymbolAddress((void**)&fcTl, g_fcTl);
    cudaGetSymbolAddress((void**)&w1Th, g_w1Th);
    cudaGetSymbolAddress((void**)&w1Tl, g_w1Tl);
    cudaGetSymbolAddress((void**)&w2Th, g_w2Th);
    cudaGetSymbolAddress((void**)&w2Tl, g_w2Tl);

    cudaFuncSetAttribute(gemm_tc<0>, cudaFuncAttributeMaxDynamicSharedMemorySize, GEMM_SMEM);
    cudaFuncSetAttribute(gemm_tc<1>, cudaFuncAttributeMaxDynamicSharedMemorySize, GEMM_SMEM);
    cudaFuncSetAttribute(gemm_tc<2>, cudaFuncAttributeMaxDynamicSharedMemorySize, GEMM_SMEM);

    // 1) xn = LN(x)
    ln_kernel<<<NM, 256>>>(x, ln_g, ln_b, xn);
    // 2) conv constants + chunked scan
    conv_setup<<<1, ND>>>(ph_re, ph_im);
    dim3 gs(ND / 256, NC, NB);
    conv_scanA<<<gs, 256>>>(xn);
    conv_scanB<<<(NB * ND) / 256, 256>>>();
    conv_scanC<<<gs, 256>>>(xn, phi_re, phi_im, lci_re, lci_im, conv);
    // 3) splits for tensor-core GEMMs
    convert_x<<<(NM * ND / 4) / 256, 256>>>(x, xh, xl);
    transpose_split<<<dim3(ND / 32, ND / 32), 256>>>(fc_w, fcTh, fcTl, ND, ND);
    transpose_split<<<dim3(NFF / 32, ND / 32), 256>>>(w1, w1Th, w1Tl, ND, NFF);
    transpose_split<<<dim3(ND / 32, NFF / 32), 256>>>(w2, w2Th, w2Tl, NFF, ND);
    // 4) y = silu(x @ fc_w + fc_b)
    gemm_tc<0><<<dim3(ND / NTG, NM / MT), 256, GEMM_SMEM>>>(
        xh, xl, fcTh, fcTl, fc_b, nullptr, y, nullptr, nullptr, NM, ND, ND);
    // 5) x2 = conv*y + x ; x3 = LN(x2) (bf16 split)
    x2_ln_kernel<<<NM, 256>>>(x, conv, y, ln_g, ln_b, x2, x3h, x3l);
    // 6) t1 = silu(x3 @ w1 + b1) (bf16 split)
    gemm_tc<1><<<dim3(NFF / NTG, NM / MT), 256, GEMM_SMEM>>>(
        x3h, x3l, w1Th, w1Tl, b1, nullptr, nullptr, t1h, t1l, NM, NFF, ND);
    // 7) out = x2 + t1 @ w2 + b2
    gemm_tc<2><<<dim3(ND / NTG, NM / MT), 256, GEMM_SMEM>>>(
        t1h, t1l, w2Th, w2Tl, b2, x2, out, nullptr, nullptr, NM, ND, NFF);
}